// round 3
// baseline (speedup 1.0000x reference)
#include <cuda_runtime.h>
#include <cuda_bf16.h>

#define NNODES 50000
#define NEDGES 800000
#define HD 128      // H*D
#define CINF 256
#define COUTF 128
#define DSK 32
#define NB_SCAN 196 // ceil(50000/256)

// ---------------- device scratch (static: no allocation allowed) ----------------
__device__ float g_q[NNODES * HD];
__device__ float g_k[NNODES * HD];
__device__ float g_v[NNODES * HD];
__device__ float g_skip[NNODES * DSK];
__device__ float g_yA[NNODES * DSK];
__device__ int   g_cnt[NNODES];
__device__ int   g_rs[NNODES];
__device__ int   g_wp[NNODES];
__device__ int   g_bsum[256];
__device__ int   g_eid[NEDGES];

// ---------------- CSR build ----------------
__global__ void k_zero() {
    int i = blockIdx.x * blockDim.x + threadIdx.x;
    if (i < NNODES) g_cnt[i] = 0;
}

__global__ void k_count(const int* __restrict__ dst) {
    int i = blockIdx.x * blockDim.x + threadIdx.x;
    if (i < NEDGES) atomicAdd(&g_cnt[dst[i]], 1);
}

__global__ void k_scan1() {
    __shared__ int sh[256];
    int t = threadIdx.x;
    int i = blockIdx.x * 256 + t;
    int v = (i < NNODES) ? g_cnt[i] : 0;
    sh[t] = v;
    __syncthreads();
    for (int off = 1; off < 256; off <<= 1) {
        int a = (t >= off) ? sh[t - off] : 0;
        __syncthreads();
        sh[t] += a;
        __syncthreads();
    }
    if (i < NNODES) g_rs[i] = sh[t] - v;   // exclusive within block
    if (t == 255) g_bsum[blockIdx.x] = sh[255];
}

__global__ void k_scan2(int nb) {
    if (threadIdx.x == 0 && blockIdx.x == 0) {
        int run = 0;
        for (int b = 0; b < nb; b++) { int tv = g_bsum[b]; g_bsum[b] = run; run += tv; }
    }
}

__global__ void k_scan3() {
    int i = blockIdx.x * 256 + threadIdx.x;
    if (i < NNODES) {
        int v = g_rs[i] + g_bsum[blockIdx.x];
        g_rs[i] = v;
        g_wp[i] = v;
    }
}

__global__ void k_scatter(const int* __restrict__ dst) {
    int i = blockIdx.x * blockDim.x + threadIdx.x;
    if (i < NEDGES) {
        int d = dst[i];
        int pos = atomicAdd(&g_wp[d], 1);
        g_eid[pos] = i;
    }
}

// ---------------- precompute: q,k,v,skip = [x, x*t] @ W + b ----------------
// block: 256 threads, 32 nodes. smem holds y0 transposed [feature][node] (pad 33).
// 13 col-blocks of 32 cols (4 q, 4 k, 4 v, 1 skip); warp w takes cb = w, w+8.
// thread: node = lane, 32 accumulators; weight loads warp-uniform float4.
__global__ void __launch_bounds__(256) k_pre(
    const float* __restrict__ x, const float* __restrict__ t,
    const float* __restrict__ Wq, const float* __restrict__ bq,
    const float* __restrict__ Wk, const float* __restrict__ bk,
    const float* __restrict__ Wv, const float* __restrict__ bv,
    const float* __restrict__ Wsk, const float* __restrict__ bsk)
{
    __shared__ float y0s[CINF * 33];
    int n0 = blockIdx.x * 32;

    for (int e = threadIdx.x; e < 32 * CINF; e += 256) {
        int i = e >> 8;        // node within tile
        int f = e & 255;       // feature
        int n = n0 + i;
        float val = 0.0f;
        if (n < NNODES) {
            if (f < COUTF) val = x[n * COUTF + f];
            else           val = x[n * COUTF + f - COUTF] * t[n];
        }
        y0s[f * 33 + i] = val;
    }
    __syncthreads();

    int lane = threadIdx.x & 31;
    int w = threadIdx.x >> 5;
    int node = n0 + lane;

    for (int cb = w; cb < 13; cb += 8) {
        const float* W; const float* B; float* O; int nc; int c0;
        if (cb < 4)        { W = Wq;  B = bq;  O = g_q;    nc = HD;  c0 = cb * 32; }
        else if (cb < 8)   { W = Wk;  B = bk;  O = g_k;    nc = HD;  c0 = (cb - 4) * 32; }
        else if (cb < 12)  { W = Wv;  B = bv;  O = g_v;    nc = HD;  c0 = (cb - 8) * 32; }
        else               { W = Wsk; B = bsk; O = g_skip; nc = DSK; c0 = 0; }

        float acc[32];
        #pragma unroll
        for (int c = 0; c < 32; c++) acc[c] = B[c0 + c];

        for (int kk = 0; kk < CINF; kk++) {
            float yv = y0s[kk * 33 + lane];
            const float4* wr = (const float4*)(W + kk * nc + c0);
            #pragma unroll
            for (int q4 = 0; q4 < 8; q4++) {
                float4 wv = __ldg(&wr[q4]);
                acc[q4 * 4 + 0] = fmaf(yv, wv.x, acc[q4 * 4 + 0]);
                acc[q4 * 4 + 1] = fmaf(yv, wv.y, acc[q4 * 4 + 1]);
                acc[q4 * 4 + 2] = fmaf(yv, wv.z, acc[q4 * 4 + 2]);
                acc[q4 * 4 + 3] = fmaf(yv, wv.w, acc[q4 * 4 + 3]);
            }
        }
        if (node < NNODES) {
            float4* orow = (float4*)(O + node * nc + c0);
            #pragma unroll
            for (int q4 = 0; q4 < 8; q4++)
                orow[q4] = make_float4(acc[q4 * 4 + 0], acc[q4 * 4 + 1],
                                       acc[q4 * 4 + 2], acc[q4 * 4 + 3]);
        }
    }
}

// ---------------- node-parallel online-softmax aggregation ----------------
// one warp per node. lane = d (0..31), H=4 heads in registers.
__global__ void __launch_bounds__(256) k_attn(
    const int* __restrict__ srcArr, const float* __restrict__ ew,
    const float* __restrict__ We, const float* __restrict__ be)
{
    __shared__ float Wes[HD], bes[HD];
    if (threadIdx.x < HD) { Wes[threadIdx.x] = We[threadIdx.x]; bes[threadIdx.x] = be[threadIdx.x]; }
    __syncthreads();

    int w = threadIdx.x >> 5, lane = threadIdx.x & 31;
    int node = blockIdx.x * 8 + w;
    if (node >= NNODES) return;

    float ql[4], Wel[4], bel[4];
    #pragma unroll
    for (int h = 0; h < 4; h++) {
        ql[h]  = g_q[node * HD + h * 32 + lane];
        Wel[h] = Wes[h * 32 + lane];
        bel[h] = bes[h * 32 + lane];
    }
    float m[4] = {-1e30f, -1e30f, -1e30f, -1e30f};
    float s[4] = {0.f, 0.f, 0.f, 0.f};
    float acc[4] = {0.f, 0.f, 0.f, 0.f};

    int cnt = g_cnt[node];
    int rs  = g_rs[node];

    for (int base = 0; base < cnt; base += 32) {
        int j = base + lane;
        int sid = 0; float w0 = 0.f;
        if (j < cnt) {
            int eid = g_eid[rs + j];
            sid = srcArr[eid];
            w0  = ew[eid];
        }
        int lim = min(32, cnt - base);
        for (int i = 0; i < lim; i++) {
            int   si = __shfl_sync(0xffffffffu, sid, i);
            float wv = __shfl_sync(0xffffffffu, w0, i);
            const float* kr = g_k + si * HD;
            const float* vr = g_v + si * HD;
            float kv[4], vv[4], eh[4], part[4];
            #pragma unroll
            for (int h = 0; h < 4; h++) {
                kv[h] = __ldg(kr + h * 32 + lane);
                vv[h] = __ldg(vr + h * 32 + lane);
            }
            #pragma unroll
            for (int h = 0; h < 4; h++) {
                eh[h] = fmaf(wv, Wel[h], bel[h]);
                part[h] = ql[h] * (kv[h] + eh[h]);
            }
            #pragma unroll
            for (int off = 16; off > 0; off >>= 1) {
                #pragma unroll
                for (int h = 0; h < 4; h++)
                    part[h] += __shfl_xor_sync(0xffffffffu, part[h], off);
            }
            #pragma unroll
            for (int h = 0; h < 4; h++) {
                float a = part[h] * 0.17677669529663687f; // 1/sqrt(32)
                float vpe = vv[h] + eh[h];
                if (a > m[h]) {               // warp-uniform branch
                    float sc = __expf(m[h] - a);
                    s[h]   = fmaf(s[h], sc, 1.0f);
                    acc[h] = fmaf(acc[h], sc, vpe);
                    m[h] = a;
                } else {
                    float p = __expf(a - m[h]);
                    s[h] += p;
                    acc[h] = fmaf(p, vpe, acc[h]);
                }
            }
        }
    }

    float res = 0.f;
    #pragma unroll
    for (int h = 0; h < 4; h++) res += acc[h] / (s[h] + 1e-16f);
    res *= 0.25f;
    float yv = tanhf(res + g_skip[node * DSK + lane]);
    g_yA[node * DSK + lane] = yv;
}

// ---------------- MLP (32 -> 256) + tanh + final affine ----------------
__global__ void __launch_bounds__(256) k_mlp(
    const float* __restrict__ x, const float* __restrict__ Wm,
    const float* __restrict__ bm, float* __restrict__ out)
{
    __shared__ float ys[DSK * 33];
    __shared__ float y2s[32 * 257];
    int n0 = blockIdx.x * 32;

    for (int e = threadIdx.x; e < 32 * DSK; e += 256) {
        int i = e >> 5;
        int f = e & 31;
        int n = n0 + i;
        ys[f * 33 + i] = (n < NNODES) ? g_yA[n * DSK + f] : 0.f;
    }
    __syncthreads();

    int w = threadIdx.x >> 5, lane = threadIdx.x & 31;
    int c0 = w * 32;
    float acc[32];
    #pragma unroll
    for (int c = 0; c < 32; c++) acc[c] = bm[c0 + c];
    #pragma unroll
    for (int kk = 0; kk < DSK; kk++) {
        float yv = ys[kk * 33 + lane];
        const float4* wr = (const float4*)(Wm + kk * 256 + c0);
        #pragma unroll
        for (int q4 = 0; q4 < 8; q4++) {
            float4 wv = __ldg(&wr[q4]);
            acc[q4 * 4 + 0] = fmaf(yv, wv.x, acc[q4 * 4 + 0]);
            acc[q4 * 4 + 1] = fmaf(yv, wv.y, acc[q4 * 4 + 1]);
            acc[q4 * 4 + 2] = fmaf(yv, wv.z, acc[q4 * 4 + 2]);
            acc[q4 * 4 + 3] = fmaf(yv, wv.w, acc[q4 * 4 + 3]);
        }
    }
    #pragma unroll
    for (int c = 0; c < 32; c++)
        y2s[lane * 257 + c0 + c] = tanhf(acc[c]);
    __syncthreads();

    for (int e = threadIdx.x; e < 32 * COUTF; e += 256) {
        int i = e >> 7;
        int c = e & 127;
        int n = n0 + i;
        if (n < NNODES) {
            float sc = y2s[i * 257 + c];
            float sh = y2s[i * 257 + 128 + c];
            out[n * COUTF + c] = fmaf(x[n * COUTF + c], sc, sh);
        }
    }
}

// ---------------- launch ----------------
extern "C" void kernel_launch(void* const* d_in, const int* in_sizes, int n_in,
                              void* d_out, int out_size)
{
    const float* x   = (const float*)d_in[0];
    const float* t   = (const float*)d_in[1];
    const int*   ei  = (const int*)  d_in[2];
    const float* ew  = (const float*)d_in[3];
    const float* Wq  = (const float*)d_in[4];
    const float* bq  = (const float*)d_in[5];
    const float* Wk  = (const float*)d_in[6];
    const float* bk  = (const float*)d_in[7];
    const float* Wv  = (const float*)d_in[8];
    const float* bv  = (const float*)d_in[9];
    const float* We  = (const float*)d_in[10];
    const float* be  = (const float*)d_in[11];
    const float* Wsk = (const float*)d_in[12];
    const float* bsk = (const float*)d_in[13];
    const float* Wm  = (const float*)d_in[14];
    const float* bm  = (const float*)d_in[15];
    float* out = (float*)d_out;

    const int* src = ei;
    const int* dst = ei + NEDGES;

    k_zero<<<NB_SCAN, 256>>>();
    k_count<<<(NEDGES + 255) / 256, 256>>>(dst);
    k_scan1<<<NB_SCAN, 256>>>();
    k_scan2<<<1, 1>>>(NB_SCAN);
    k_scan3<<<NB_SCAN, 256>>>();
    k_scatter<<<(NEDGES + 255) / 256, 256>>>(dst);
    k_pre<<<(NNODES + 31) / 32, 256>>>(x, t, Wq, bq, Wk, bk, Wv, bv, Wsk, bsk);
    k_attn<<<(NNODES + 7) / 8, 256>>>(src, ew, We, be);
    k_mlp<<<(NNODES + 31) / 32, 256>>>(x, Wm, bm, out);
}

// round 6
// speedup vs baseline: 1.0344x; 1.0344x over previous
#include <cuda_runtime.h>
#include <cuda_bf16.h>

#define NNODES 50000
#define NEDGES 800000
#define HD 128      // H*D
#define CINF 256
#define COUTF 128
#define DSK 32

// ---------------- device scratch (static: no allocation allowed) ----------------
__device__ float g_q[NNODES * HD];
__device__ float g_k[NNODES * HD];
__device__ float g_v[NNODES * HD];
__device__ float g_skip[NNODES * DSK];
__device__ float g_yA[NNODES * DSK];
__device__ int   g_cnt[NNODES];
__device__ int   g_rs[NNODES];
__device__ int   g_wp[NNODES];
__device__ int   g_srcs[NEDGES];   // src node ids sorted into CSR order
__device__ float g_ews[NEDGES];    // edge weights sorted into CSR order

// ---------------- f32x2 packed-FMA helpers (sm_10x FFMA2) ----------------
__device__ __forceinline__ unsigned long long pack2(float a, float b) {
    unsigned long long r;
    asm("mov.b64 %0, {%1, %2};" : "=l"(r) : "f"(a), "f"(b));
    return r;
}
__device__ __forceinline__ void unpack2(unsigned long long v, float& a, float& b) {
    asm("mov.b64 {%0, %1}, %2;" : "=f"(a), "=f"(b) : "l"(v));
}
__device__ __forceinline__ unsigned long long ffma2(unsigned long long a,
                                                    unsigned long long b,
                                                    unsigned long long c) {
    unsigned long long d;
    asm("fma.rn.f32x2 %0, %1, %2, %3;" : "=l"(d) : "l"(a), "l"(b), "l"(c));
    return d;
}

// ---------------- CSR build ----------------
__global__ void k_zero() {
    int i = blockIdx.x * blockDim.x + threadIdx.x;
    if (i < NNODES) g_cnt[i] = 0;
}

__global__ void k_count(const int* __restrict__ dst) {
    int i = blockIdx.x * blockDim.x + threadIdx.x;
    if (i < NEDGES) atomicAdd(&g_cnt[dst[i]], 1);
}

// single-block cooperative exclusive scan of g_cnt -> g_rs, g_wp
__global__ void __launch_bounds__(1024) k_scan() {
    __shared__ int sh[1024];
    int t = threadIdx.x;
    const int C = 49;               // 1024 * 49 = 50176 >= NNODES
    int b0 = t * C;
    int sum = 0;
    for (int i = 0; i < C; i++) {
        int idx = b0 + i;
        if (idx < NNODES) sum += g_cnt[idx];
    }
    sh[t] = sum;
    __syncthreads();
    for (int off = 1; off < 1024; off <<= 1) {
        int a = (t >= off) ? sh[t - off] : 0;
        __syncthreads();
        sh[t] += a;
        __syncthreads();
    }
    int run = sh[t] - sum;          // exclusive prefix for this thread's chunk
    for (int i = 0; i < C; i++) {
        int idx = b0 + i;
        if (idx < NNODES) {
            int v = g_cnt[idx];
            g_rs[idx] = run;
            g_wp[idx] = run;
            run += v;
        }
    }
}

// scatter src + weight directly into CSR order (no eid indirection later)
__global__ void k_scatter(const int* __restrict__ src, const int* __restrict__ dst,
                          const float* __restrict__ ew) {
    int i = blockIdx.x * blockDim.x + threadIdx.x;
    if (i < NEDGES) {
        int d = dst[i];
        int pos = atomicAdd(&g_wp[d], 1);
        g_srcs[pos] = src[i];
        g_ews[pos]  = ew[i];
    }
}

// ---------------- precompute: q,k,v,skip = [x, x*t] @ W + b  (FFMA2 path) ----------------
__global__ void __launch_bounds__(256) k_pre(
    const float* __restrict__ x, const float* __restrict__ t,
    const float* __restrict__ Wq, const float* __restrict__ bq,
    const float* __restrict__ Wk, const float* __restrict__ bk,
    const float* __restrict__ Wv, const float* __restrict__ bv,
    const float* __restrict__ Wsk, const float* __restrict__ bsk)
{
    __shared__ float y0s[CINF * 33];
    int n0 = blockIdx.x * 32;

    for (int e = threadIdx.x; e < 32 * CINF; e += 256) {
        int i = e >> 8;        // node within tile
        int f = e & 255;       // feature
        int n = n0 + i;
        float val = 0.0f;
        if (n < NNODES) {
            if (f < COUTF) val = x[n * COUTF + f];
            else           val = x[n * COUTF + f - COUTF] * t[n];
        }
        y0s[f * 33 + i] = val;
    }
    __syncthreads();

    int lane = threadIdx.x & 31;
    int w = threadIdx.x >> 5;
    int node = n0 + lane;

    for (int cb = w; cb < 13; cb += 8) {
        const float* W; const float* B; float* O; int nc; int c0;
        if (cb < 4)        { W = Wq;  B = bq;  O = g_q;    nc = HD;  c0 = cb * 32; }
        else if (cb < 8)   { W = Wk;  B = bk;  O = g_k;    nc = HD;  c0 = (cb - 4) * 32; }
        else if (cb < 12)  { W = Wv;  B = bv;  O = g_v;    nc = HD;  c0 = (cb - 8) * 32; }
        else               { W = Wsk; B = bsk; O = g_skip; nc = DSK; c0 = 0; }

        unsigned long long acc2[16];
        #pragma unroll
        for (int c = 0; c < 16; c++) acc2[c] = pack2(B[c0 + 2 * c], B[c0 + 2 * c + 1]);

        for (int kk = 0; kk < CINF; kk++) {
            float yv = y0s[kk * 33 + lane];
            unsigned long long yy = pack2(yv, yv);
            const ulonglong2* wr = (const ulonglong2*)(W + kk * nc + c0);
            #pragma unroll
            for (int q4 = 0; q4 < 8; q4++) {
                ulonglong2 wv = __ldg(&wr[q4]);
                acc2[q4 * 2 + 0] = ffma2(yy, wv.x, acc2[q4 * 2 + 0]);
                acc2[q4 * 2 + 1] = ffma2(yy, wv.y, acc2[q4 * 2 + 1]);
            }
        }
        if (node < NNODES) {
            ulonglong2* orow = (ulonglong2*)(O + node * nc + c0);
            #pragma unroll
            for (int q4 = 0; q4 < 8; q4++) {
                ulonglong2 ov;
                ov.x = acc2[q4 * 2 + 0];
                ov.y = acc2[q4 * 2 + 1];
                orow[q4] = ov;
            }
        }
    }
}

// ---------------- node-parallel online-softmax aggregation ----------------
// one warp per node. lane = h*8 + dgrp : head h=lane>>3, 4 d's per lane (float4).
// alpha = (q·k + w_e*(q·We) + q·be)/sqrt(D)
// agg   = [ Σp·v + (Σp·w_e)·We + (Σp)·be ] / (Σp + 1e-16)
__global__ void __launch_bounds__(256) k_attn(
    const float* __restrict__ We, const float* __restrict__ be)
{
    int w = threadIdx.x >> 5, lane = threadIdx.x & 31;
    int node = blockIdx.x * 8 + w;
    if (node >= NNODES) return;

    float4 q4  = __ldg((const float4*)(g_q + node * HD) + lane);
    float4 We4 = __ldg((const float4*)We + lane);
    float4 be4 = __ldg((const float4*)be + lane);

    // per-head scalars q·We, q·be (reduced within 8-lane head group)
    float qWe = q4.x * We4.x + q4.y * We4.y + q4.z * We4.z + q4.w * We4.w;
    float qbe = q4.x * be4.x + q4.y * be4.y + q4.z * be4.z + q4.w * be4.w;
    #pragma unroll
    for (int off = 4; off > 0; off >>= 1) {
        qWe += __shfl_xor_sync(0xffffffffu, qWe, off);
        qbe += __shfl_xor_sync(0xffffffffu, qbe, off);
    }

    float m = -1e30f, s = 0.f, accW = 0.f;
    float4 acc4 = make_float4(0.f, 0.f, 0.f, 0.f);
    const float invs = 0.17677669529663687f;  // 1/sqrt(32)

    int cnt = g_cnt[node];
    int rs  = g_rs[node];

    for (int base = 0; base < cnt; base += 32) {
        int j = base + lane;
        int sid = 0; float w0 = 0.f;
        if (j < cnt) { sid = g_srcs[rs + j]; w0 = g_ews[rs + j]; }
        int lim = min(32, cnt - base);
        for (int i = 0; i < lim; i++) {
            int   si = __shfl_sync(0xffffffffu, sid, i);
            float wv = __shfl_sync(0xffffffffu, w0, i);
            float4 k4 = __ldg((const float4*)(g_k + si * HD) + lane);
            float4 v4 = __ldg((const float4*)(g_v + si * HD) + lane);
            float dt = q4.x * k4.x + q4.y * k4.y + q4.z * k4.z + q4.w * k4.w;
            dt += __shfl_xor_sync(0xffffffffu, dt, 4);
            dt += __shfl_xor_sync(0xffffffffu, dt, 2);
            dt += __shfl_xor_sync(0xffffffffu, dt, 1);
            float a  = (dt + wv * qWe + qbe) * invs;
            float nm = fmaxf(m, a);
            float sc = __expf(m - nm);   // 1.0 when m unchanged
            float p  = __expf(a - nm);
            m = nm;
            s    = fmaf(s,    sc, p);
            accW = fmaf(accW, sc, p * wv);
            acc4.x = fmaf(acc4.x, sc, p * v4.x);
            acc4.y = fmaf(acc4.y, sc, p * v4.y);
            acc4.z = fmaf(acc4.z, sc, p * v4.z);
            acc4.w = fmaf(acc4.w, sc, p * v4.w);
        }
    }

    float inv = 1.f / (s + 1e-16f);
    float4 r;
    r.x = (acc4.x + accW * We4.x + s * be4.x) * inv;
    r.y = (acc4.y + accW * We4.y + s * be4.y) * inv;
    r.z = (acc4.z + accW * We4.z + s * be4.z) * inv;
    r.w = (acc4.w + accW * We4.w + s * be4.w) * inv;

    // mean over heads: lanes j, j+8, j+16, j+24 hold the 4 heads of d-slot j
    #pragma unroll
    for (int off = 8; off <= 16; off <<= 1) {
        r.x += __shfl_xor_sync(0xffffffffu, r.x, off);
        r.y += __shfl_xor_sync(0xffffffffu, r.y, off);
        r.z += __shfl_xor_sync(0xffffffffu, r.z, off);
        r.w += __shfl_xor_sync(0xffffffffu, r.w, off);
    }

    if (lane < 8) {
        float4 sk = __ldg((const float4*)(g_skip + node * DSK) + lane);
        float4 o;
        o.x = tanhf(fmaf(r.x, 0.25f, sk.x));
        o.y = tanhf(fmaf(r.y, 0.25f, sk.y));
        o.z = tanhf(fmaf(r.z, 0.25f, sk.z));
        o.w = tanhf(fmaf(r.w, 0.25f, sk.w));
        ((float4*)(g_yA + node * DSK))[lane] = o;
    }
}

// ---------------- MLP (32 -> 256) + tanh + final affine (FFMA2 path) ----------------
__global__ void __launch_bounds__(256) k_mlp(
    const float* __restrict__ x, const float* __restrict__ Wm,
    const float* __restrict__ bm, float* __restrict__ out)
{
    __shared__ float ys[DSK * 33];
    __shared__ float y2s[32 * 257];
    int n0 = blockIdx.x * 32;

    for (int e = threadIdx.x; e < 32 * DSK; e += 256) {
        int i = e >> 5;
        int f = e & 31;
        int n = n0 + i;
        ys[f * 33 + i] = (n < NNODES) ? g_yA[n * DSK + f] : 0.f;
    }
    __syncthreads();

    int w = threadIdx.x >> 5, lane = threadIdx.x & 31;
    int c0 = w * 32;
    unsigned long long acc2[16];
    #pragma unroll
    for (int c = 0; c < 16; c++) acc2[c] = pack2(bm[c0 + 2 * c], bm[c0 + 2 * c + 1]);
    #pragma unroll
    for (int kk = 0; kk < DSK; kk++) {
        float yv = ys[kk * 33 + lane];
        unsigned long long yy = pack2(yv, yv);
        const ulonglong2* wr = (const ulonglong2*)(Wm + kk * 256 + c0);
        #pragma unroll
        for (int q4 = 0; q4 < 8; q4++) {
            ulonglong2 wv = __ldg(&wr[q4]);
            acc2[q4 * 2 + 0] = ffma2(yy, wv.x, acc2[q4 * 2 + 0]);
            acc2[q4 * 2 + 1] = ffma2(yy, wv.y, acc2[q4 * 2 + 1]);
        }
    }
    #pragma unroll
    for (int c = 0; c < 16; c++) {
        float a, b;
        unpack2(acc2[c], a, b);
        y2s[lane * 257 + c0 + 2 * c]     = tanhf(a);
        y2s[lane * 257 + c0 + 2 * c + 1] = tanhf(b);
    }
    __syncthreads();

    for (int e = threadIdx.x; e < 32 * COUTF; e += 256) {
        int i = e >> 7;
        int c = e & 127;
        int n = n0 + i;
        if (n < NNODES) {
            float sc = y2s[i * 257 + c];
            float sh = y2s[i * 257 + 128 + c];
            out[n * COUTF + c] = fmaf(x[n * COUTF + c], sc, sh);
        }
    }
}

// ---------------- launch ----------------
extern "C" void kernel_launch(void* const* d_in, const int* in_sizes, int n_in,
                              void* d_out, int out_size)
{
    const float* x   = (const float*)d_in[0];
    const float* t   = (const float*)d_in[1];
    const int*   ei  = (const int*)  d_in[2];
    const float* ew  = (const float*)d_in[3];
    const float* Wq  = (const float*)d_in[4];
    const float* bq  = (const float*)d_in[5];
    const float* Wk  = (const float*)d_in[6];
    const float* bk  = (const float*)d_in[7];
    const float* Wv  = (const float*)d_in[8];
    const float* bv  = (const float*)d_in[9];
    const float* We  = (const float*)d_in[10];
    const float* be  = (const float*)d_in[11];
    const float* Wsk = (const float*)d_in[12];
    const float* bsk = (const float*)d_in[13];
    const float* Wm  = (const float*)d_in[14];
    const float* bm  = (const float*)d_in[15];
    float* out = (float*)d_out;

    const int* src = ei;
    const int* dst = ei + NEDGES;

    // order chosen so the profiler's fixed capture slot lands on k_pre
    k_zero<<<(NNODES + 255) / 256, 256>>>();
    k_count<<<(NEDGES + 255) / 256, 256>>>(dst);
    k_scan<<<1, 1024>>>();
    k_pre<<<(NNODES + 31) / 32, 256>>>(x, t, Wq, bq, Wk, bk, Wv, bv, Wsk, bsk);
    k_scatter<<<(NEDGES + 255) / 256, 256>>>(src, dst, ew);
    k_attn<<<(NNODES + 7) / 8, 256>>>(We, be);
    k_mlp<<<(NNODES + 31) / 32, 256>>>(x, Wm, bm, out);
}